// round 15
// baseline (speedup 1.0000x reference)
#include <cuda_runtime.h>
#include <cstdint>
#include <math.h>

// y_true [B,1024] fp32, target [B,1024] fp32 -> scalar fp32 loss.
#define NCOLS   1024
#define NBLK    444            // 148 SMs * 3 resident blocks (80 regs/thread)
#define NWARPS  (NBLK * 8)
#define NPAIRS  (NWARPS / 2)

__device__ double g_pt[NBLK];
__device__ double g_ce[NBLK];
__device__ unsigned int g_count = 0;   // last-block-done counter

__device__ __forceinline__ float wval(int x) {
    const int pc = __popc(x);
    float w = ((pc & 1) ? 6.0f       : 1.0f)
            * ((pc & 2) ? 36.0f      : 1.0f)
            * ((pc & 4) ? 1296.0f    : 1.0f)
            * ((pc & 8) ? 1679616.0f : 1.0f);
    return (x == 0) ? 0.0f : w;   // 6^popc(x), zeroed at x==0; exact in fp32
}

// ---------------------------------------------------------------------------
// R11 one-row pipeline + balanced remainder: every warp does exactly
// floor(B/NWARPS) full rows; the B mod NWARPS leftover rows are split in half
// across warp PAIRS (even warp: cols 0-511, odd warp: cols 512-1023) with a
// single named-barrier argmax merge. Max warp work: m+0.5 rows (was m+1).
// ---------------------------------------------------------------------------
__global__ void __launch_bounds__(256, 3)
fused_kernel(const float* __restrict__ y, const float* __restrict__ target,
             float* __restrict__ out, int B) {
    // W[p][i] = wval(i ^ p): weight of col x=4g+j for class t=4*tg+tl is
    // W[tl][4*(g^tg)+j]  (bit-disjoint split, works for any column range).
    __shared__ float W[4][NCOLS];
    __shared__ uint2 pex[4][2];    // per-pair argmax exchange (maxbits, idx)
    const int tid  = threadIdx.x;
    const int lane = tid & 31;
    const int wid  = tid >> 5;
    for (int i = tid; i < NCOLS; i += 256) {
        #pragma unroll
        for (int p = 0; p < 4; p++) W[p][i] = wval(i ^ p);
    }
    __syncthreads();

    const int gwarp = blockIdx.x * 8 + wid;
    const int pairP = gwarp >> 1;
    const int half  = gwarp & 1;
    const int q     = wid >> 1;          // pair index within block (0..3)

    const int m   = B / NWARPS;          // full rows per warp
    const int rem = B - m * NWARPS;      // rows split across pairs

    float pt32 = 0.0f;   // fp32 within-warp is exact enough (budget ~140 abs)
    float ce32 = 0.0f;

    // ---- Main phase: m contiguous rows per warp, R11 pipeline ----
    if (m > 0) {
        int b = pairP * 2 * m + half * m;
        float best = -1.0f;
        int   bidx = 0;
        float4 yv[8];

        // Prologue: load row b's target + y; per-lane argmax of target.
        {
            const float4* tp = reinterpret_cast<const float4*>(target + (size_t)b * NCOLS);
            const float4* yp = reinterpret_cast<const float4*>(y      + (size_t)b * NCOLS);
            float4 tv[8];
            #pragma unroll
            for (int i = 0; i < 8; i++) {
                tv[i] = __ldcs(&tp[i * 32 + lane]);
                yv[i] = __ldcs(&yp[i * 32 + lane]);
            }
            #pragma unroll
            for (int i = 0; i < 8; i++) {
                const int base = (i * 32 + lane) * 4;
                if (tv[i].x > best) { best = tv[i].x; bidx = base;     }
                if (tv[i].y > best) { best = tv[i].y; bidx = base + 1; }
                if (tv[i].z > best) { best = tv[i].z; bidx = base + 2; }
                if (tv[i].w > best) { best = tv[i].w; bidx = base + 3; }
            }
        }

        for (int iter = 0; iter < m; iter++) {
            const bool last = (iter == m - 1);
            const int bn = last ? b : b + 1;   // clamped prefetch on last iter
            const float4* tpn = reinterpret_cast<const float4*>(target + (size_t)bn * NCOLS);
            const float4* ypn = reinterpret_cast<const float4*>(y      + (size_t)bn * NCOLS);

            // (1) issue next target row loads (front-batched).
            float4 tn[8];
            #pragma unroll
            for (int i = 0; i < 8; i++) tn[i] = __ldcs(&tpn[i * 32 + lane]);

            // (2) cross-lane argmax for row b from carried (best,bidx): no wait.
            const unsigned int mybits  = __float_as_uint(best);
            const unsigned int maxbits = __reduce_max_sync(0xffffffffu, mybits);
            const unsigned int cand    = (mybits == maxbits) ? (unsigned int)bidx
                                                             : 0xffffffffu;
            const int t  = (int)__reduce_min_sync(0xffffffffu, cand);
            const int tg = t >> 2;
            const float* Wt = W[t & 3];

            // (3) FMA carried yv (row b, loaded one iteration ago): no wait.
            float s0 = 0.f, s1 = 0.f, s2 = 0.f, s3 = 0.f;
            float yt = -1.0f;
            #pragma unroll
            for (int i = 0; i < 8; i++) {
                const int c4 = i * 32 + lane;
                const float4 w4 = *reinterpret_cast<const float4*>(&Wt[(c4 ^ tg) << 2]);
                s0 += w4.x * yv[i].x;
                s1 += w4.y * yv[i].y;
                s2 += w4.z * yv[i].z;
                s3 += w4.w * yv[i].w;
                if (c4 == tg) {
                    yt = (t & 1) ? ((t & 2) ? yv[i].w : yv[i].y)
                                 : ((t & 2) ? yv[i].z : yv[i].x);
                }
            }
            pt32 += (s0 + s1) + (s2 + s3);
            if (yt >= 0.0f) ce32 += __logf(yt + 1e-8f);   // one lane per warp

            // (4) issue next y row loads (front-batched; lands next iter).
            #pragma unroll
            for (int i = 0; i < 8; i++) yv[i] = __ldcs(&ypn[i * 32 + lane]);

            // (5) per-lane compare on next target row (wait covered by 2-4).
            best = -1.0f; bidx = 0;
            #pragma unroll
            for (int i = 0; i < 8; i++) {
                const int base = (i * 32 + lane) * 4;
                if (tn[i].x > best) { best = tn[i].x; bidx = base;     }
                if (tn[i].y > best) { best = tn[i].y; bidx = base + 1; }
                if (tn[i].z > best) { best = tn[i].z; bidx = base + 2; }
                if (tn[i].w > best) { best = tn[i].w; bidx = base + 3; }
            }

            b = bn;
        }
    }

    // ---- Remainder phase: split rows, half per warp, pairwise merge ----
    for (int s = pairP; s < rem; s += NPAIRS) {
        const int rs = m * NWARPS + s;
        const float4* tp = reinterpret_cast<const float4*>(target + (size_t)rs * NCOLS);
        const float4* yp = reinterpret_cast<const float4*>(y      + (size_t)rs * NCOLS);
        const int gbase = half * 128;          // this warp's float4-group range

        float4 tv[4], yh[4];
        #pragma unroll
        for (int i = 0; i < 4; i++) {
            tv[i] = __ldcs(&tp[gbase + i * 32 + lane]);
            yh[i] = __ldcs(&yp[gbase + i * 32 + lane]);
        }
        // Half-row argmax (global column indices).
        float best = -1.0f;
        int   bidx = 0;
        #pragma unroll
        for (int i = 0; i < 4; i++) {
            const int base = (gbase + i * 32 + lane) * 4;
            if (tv[i].x > best) { best = tv[i].x; bidx = base;     }
            if (tv[i].y > best) { best = tv[i].y; bidx = base + 1; }
            if (tv[i].z > best) { best = tv[i].z; bidx = base + 2; }
            if (tv[i].w > best) { best = tv[i].w; bidx = base + 3; }
        }
        const unsigned int mybits  = __float_as_uint(best);
        const unsigned int maxbits = __reduce_max_sync(0xffffffffu, mybits);
        const unsigned int cand    = (mybits == maxbits) ? (unsigned int)bidx
                                                         : 0xffffffffu;
        const int hidx = (int)__reduce_min_sync(0xffffffffu, cand);

        // Pairwise merge via smem + named barrier (64 threads).
        if (lane == 0) pex[q][half] = make_uint2(maxbits, (unsigned int)hidx);
        asm volatile("bar.sync %0, 64;" :: "r"(q + 1) : "memory");
        const uint2 pa = pex[q][0];
        const uint2 pb = pex[q][1];
        const int t = (pa.x > pb.x || (pa.x == pb.x && pa.y < pb.y))
                      ? (int)pa.y : (int)pb.y;
        const int tg = t >> 2;
        const float* Wt = W[t & 3];

        // Weighted sum over this warp's half; CE if t lands in this half.
        float s0 = 0.f, s1 = 0.f, s2 = 0.f, s3 = 0.f;
        float yt = -1.0f;
        #pragma unroll
        for (int i = 0; i < 4; i++) {
            const int c4 = gbase + i * 32 + lane;
            const float4 w4 = *reinterpret_cast<const float4*>(&Wt[(c4 ^ tg) << 2]);
            s0 += w4.x * yh[i].x;
            s1 += w4.y * yh[i].y;
            s2 += w4.z * yh[i].z;
            s3 += w4.w * yh[i].w;
            if (c4 == tg) {
                yt = (t & 1) ? ((t & 2) ? yh[i].w : yh[i].y)
                             : ((t & 2) ? yh[i].z : yh[i].x);
            }
        }
        pt32 += (s0 + s1) + (s2 + s3);
        if (yt >= 0.0f) ce32 += __logf(yt + 1e-8f);

        // Protect pex slot before any next loop trip (rare).
        asm volatile("bar.sync %0, 64;" :: "r"(q + 1) : "memory");
    }

    // Warp reduce in fp32 (fixed order), promote to double for partials.
    #pragma unroll
    for (int off = 16; off > 0; off >>= 1) {
        pt32 += __shfl_down_sync(0xffffffffu, pt32, off);
        ce32 += __shfl_down_sync(0xffffffffu, ce32, off);
    }
    __shared__ double s_pt[8];
    __shared__ double s_ce[8];
    if (lane == 0) { s_pt[wid] = (double)pt32; s_ce[wid] = (double)ce32; }
    __syncthreads();
    __shared__ bool is_last;
    if (tid == 0) {
        double bpt = 0.0, bce = 0.0;
        #pragma unroll
        for (int i = 0; i < 8; i++) { bpt += s_pt[i]; bce += s_ce[i]; }
        g_pt[blockIdx.x] = bpt;
        g_ce[blockIdx.x] = bce;
        __threadfence();
        const unsigned int arrived = atomicAdd(&g_count, 1u);
        is_last = (arrived == NBLK - 1);
    }
    __syncthreads();

    // Last block: final fixed-order reduction -> scalar loss.
    if (is_last) {
        double fpt = 0.0, fce = 0.0;
        for (int i = tid; i < NBLK; i += 256) { fpt += g_pt[i]; fce += g_ce[i]; }
        __shared__ double r_pt[256];
        __shared__ double r_ce[256];
        r_pt[tid] = fpt;
        r_ce[tid] = fce;
        __syncthreads();
        #pragma unroll
        for (int off = 128; off > 0; off >>= 1) {
            if (tid < off) {
                r_pt[tid] += r_pt[tid + off];
                r_ce[tid] += r_ce[tid + off];
            }
            __syncthreads();
        }
        if (tid == 0) {
            const double pt_loss = r_pt[0] / ((double)B * (double)NCOLS);
            const double ce_loss = -r_ce[0] / (double)B;
            out[0] = (float)(ce_loss + pt_loss);
            g_count = 0;   // reset for next graph replay
        }
    }
}

extern "C" void kernel_launch(void* const* d_in, const int* in_sizes, int n_in,
                              void* d_out, int out_size) {
    const float* y_true = (const float*)d_in[0];
    const float* target = (const float*)d_in[1];
    const int B = in_sizes[0] / NCOLS;

    fused_kernel<<<NBLK, 256>>>(y_true, target, (float*)d_out, B);
}

// round 16
// speedup vs baseline: 1.0400x; 1.0400x over previous
#include <cuda_runtime.h>
#include <cstdint>
#include <math.h>

// y_true [B,1024] fp32, target [B,1024] fp32 -> scalar fp32 loss.
#define NCOLS   1024
#define NBLK    444            // 148 SMs * 3 resident blocks (80 regs/thread)
#define NWARPS  (NBLK * 8)
#define NPAIRS  (NWARPS / 2)

__device__ double g_pt[NBLK];
__device__ double g_ce[NBLK];
__device__ unsigned int g_count = 0;   // last-block-done counter

__device__ __forceinline__ float wval(int x) {
    const int pc = __popc(x);
    float w = ((pc & 1) ? 6.0f       : 1.0f)
            * ((pc & 2) ? 36.0f      : 1.0f)
            * ((pc & 4) ? 1296.0f    : 1.0f)
            * ((pc & 8) ? 1679616.0f : 1.0f);
    return (x == 0) ? 0.0f : w;   // 6^popc(x), zeroed at x==0; exact in fp32
}

// ---------------------------------------------------------------------------
// R11 strided one-row pipeline over the first m*NWARPS rows (identical access
// pattern: all warps sweep a contiguous row band together), then the rem
// leftover rows are split in half across warp PAIRS (even warp cols 0-511,
// odd warp cols 512-1023) with one named-barrier argmax merge.
// Max warp work: m+0.5 row-equivalents (R11: m+1).
// ---------------------------------------------------------------------------
__global__ void __launch_bounds__(256, 3)
fused_kernel(const float* __restrict__ y, const float* __restrict__ target,
             float* __restrict__ out, int B) {
    // W[p][i] = wval(i ^ p): weight of col x=4g+j for class t=4*tg+tl is
    // W[tl][4*(g^tg)+j]  (bit-split is column-range agnostic).
    __shared__ float W[4][NCOLS];
    __shared__ uint2 pex[4][2];    // per-pair argmax exchange (maxbits, idx)
    const int tid  = threadIdx.x;
    const int lane = tid & 31;
    const int wid  = tid >> 5;
    for (int i = tid; i < NCOLS; i += 256) {
        #pragma unroll
        for (int p = 0; p < 4; p++) W[p][i] = wval(i ^ p);
    }
    __syncthreads();

    const int gwarp = blockIdx.x * 8 + wid;
    const int pairP = gwarp >> 1;
    const int half  = gwarp & 1;
    const int q     = wid >> 1;          // pair index within block (0..3)

    const int m     = B / NWARPS;        // full rows per warp (strided map)
    const int limit = m * NWARPS;        // rows covered by the main phase
    const int rem   = B - limit;         // rows split across pairs

    float pt32 = 0.0f;   // fp32 within-warp is exact enough (budget ~140 abs)
    float ce32 = 0.0f;

    // ---- Main phase: R11 pipeline, strided rows gwarp, gwarp+NWARPS, ... ----
    if (m > 0) {
        int   b = gwarp;
        float best = -1.0f;
        int   bidx = 0;
        float4 yv[8];

        // Prologue: load row b's target + y; per-lane argmax of target.
        {
            const float4* tp = reinterpret_cast<const float4*>(target + (size_t)b * NCOLS);
            const float4* yp = reinterpret_cast<const float4*>(y      + (size_t)b * NCOLS);
            float4 tv[8];
            #pragma unroll
            for (int i = 0; i < 8; i++) {
                tv[i] = __ldcs(&tp[i * 32 + lane]);
                yv[i] = __ldcs(&yp[i * 32 + lane]);
            }
            #pragma unroll
            for (int i = 0; i < 8; i++) {
                const int base = (i * 32 + lane) * 4;
                if (tv[i].x > best) { best = tv[i].x; bidx = base;     }
                if (tv[i].y > best) { best = tv[i].y; bidx = base + 1; }
                if (tv[i].z > best) { best = tv[i].z; bidx = base + 2; }
                if (tv[i].w > best) { best = tv[i].w; bidx = base + 3; }
            }
        }

        // Steady-state pipeline (R11 verbatim, bounded by limit).
        for (;;) {
            int bn = b + NWARPS;
            const bool last = (bn >= limit);
            if (last) bn = b;   // clamped prefetch: loaded but never accumulated
            const float4* tpn = reinterpret_cast<const float4*>(target + (size_t)bn * NCOLS);
            const float4* ypn = reinterpret_cast<const float4*>(y      + (size_t)bn * NCOLS);

            // (1) issue next target row loads (front-batched).
            float4 tn[8];
            #pragma unroll
            for (int i = 0; i < 8; i++) tn[i] = __ldcs(&tpn[i * 32 + lane]);

            // (2) cross-lane argmax for row b from carried (best,bidx): no wait.
            const unsigned int mybits  = __float_as_uint(best);
            const unsigned int maxbits = __reduce_max_sync(0xffffffffu, mybits);
            const unsigned int cand    = (mybits == maxbits) ? (unsigned int)bidx
                                                             : 0xffffffffu;
            const int t  = (int)__reduce_min_sync(0xffffffffu, cand);
            const int tg = t >> 2;
            const float* Wt = W[t & 3];

            // (3) FMA carried yv (row b, loaded one iteration ago): no wait.
            float s0 = 0.f, s1 = 0.f, s2 = 0.f, s3 = 0.f;
            float yt = -1.0f;
            #pragma unroll
            for (int i = 0; i < 8; i++) {
                const int c4 = i * 32 + lane;
                const float4 w4 = *reinterpret_cast<const float4*>(&Wt[(c4 ^ tg) << 2]);
                s0 += w4.x * yv[i].x;
                s1 += w4.y * yv[i].y;
                s2 += w4.z * yv[i].z;
                s3 += w4.w * yv[i].w;
                if (c4 == tg) {
                    yt = (t & 1) ? ((t & 2) ? yv[i].w : yv[i].y)
                                 : ((t & 2) ? yv[i].z : yv[i].x);
                }
            }
            pt32 += (s0 + s1) + (s2 + s3);
            if (yt >= 0.0f) ce32 += __logf(yt + 1e-8f);   // one lane per warp

            // (4) issue next y row loads (front-batched; lands next iter).
            #pragma unroll
            for (int i = 0; i < 8; i++) yv[i] = __ldcs(&ypn[i * 32 + lane]);

            // (5) per-lane compare on next target row (wait covered by 2-4).
            best = -1.0f; bidx = 0;
            #pragma unroll
            for (int i = 0; i < 8; i++) {
                const int base = (i * 32 + lane) * 4;
                if (tn[i].x > best) { best = tn[i].x; bidx = base;     }
                if (tn[i].y > best) { best = tn[i].y; bidx = base + 1; }
                if (tn[i].z > best) { best = tn[i].z; bidx = base + 2; }
                if (tn[i].w > best) { best = tn[i].w; bidx = base + 3; }
            }

            if (last) break;
            b = bn;
        }
    }

    // ---- Remainder phase: rows limit..B-1, half-row per warp, pair merge ----
    for (int s = pairP; s < rem; s += NPAIRS) {
        const int rs = limit + s;
        const float4* tp = reinterpret_cast<const float4*>(target + (size_t)rs * NCOLS);
        const float4* yp = reinterpret_cast<const float4*>(y      + (size_t)rs * NCOLS);
        const int gbase = half * 128;          // this warp's float4-group range

        float4 tv[4], yh[4];
        #pragma unroll
        for (int i = 0; i < 4; i++) {
            tv[i] = __ldcs(&tp[gbase + i * 32 + lane]);
            yh[i] = __ldcs(&yp[gbase + i * 32 + lane]);
        }
        // Half-row argmax (global column indices).
        float best = -1.0f;
        int   bidx = 0;
        #pragma unroll
        for (int i = 0; i < 4; i++) {
            const int base = (gbase + i * 32 + lane) * 4;
            if (tv[i].x > best) { best = tv[i].x; bidx = base;     }
            if (tv[i].y > best) { best = tv[i].y; bidx = base + 1; }
            if (tv[i].z > best) { best = tv[i].z; bidx = base + 2; }
            if (tv[i].w > best) { best = tv[i].w; bidx = base + 3; }
        }
        const unsigned int mybits  = __float_as_uint(best);
        const unsigned int maxbits = __reduce_max_sync(0xffffffffu, mybits);
        const unsigned int cand    = (mybits == maxbits) ? (unsigned int)bidx
                                                         : 0xffffffffu;
        const int hidx = (int)__reduce_min_sync(0xffffffffu, cand);

        // Pairwise merge via smem + named barrier (64 threads).
        if (lane == 0) pex[q][half] = make_uint2(maxbits, (unsigned int)hidx);
        asm volatile("bar.sync %0, 64;" :: "r"(q + 1) : "memory");
        const uint2 pa = pex[q][0];
        const uint2 pb = pex[q][1];
        const int t = (pa.x > pb.x || (pa.x == pb.x && pa.y < pb.y))
                      ? (int)pa.y : (int)pb.y;
        const int tg = t >> 2;
        const float* Wt = W[t & 3];

        // Weighted sum over this warp's half; CE if t lands in this half.
        float s0 = 0.f, s1 = 0.f, s2 = 0.f, s3 = 0.f;
        float yt = -1.0f;
        #pragma unroll
        for (int i = 0; i < 4; i++) {
            const int c4 = gbase + i * 32 + lane;
            const float4 w4 = *reinterpret_cast<const float4*>(&Wt[(c4 ^ tg) << 2]);
            s0 += w4.x * yh[i].x;
            s1 += w4.y * yh[i].y;
            s2 += w4.z * yh[i].z;
            s3 += w4.w * yh[i].w;
            if (c4 == tg) {
                yt = (t & 1) ? ((t & 2) ? yh[i].w : yh[i].y)
                             : ((t & 2) ? yh[i].z : yh[i].x);
            }
        }
        pt32 += (s0 + s1) + (s2 + s3);
        if (yt >= 0.0f) ce32 += __logf(yt + 1e-8f);

        // Protect pex slot before any next loop trip (rare).
        asm volatile("bar.sync %0, 64;" :: "r"(q + 1) : "memory");
    }

    // Warp reduce in fp32 (fixed order), promote to double for partials.
    #pragma unroll
    for (int off = 16; off > 0; off >>= 1) {
        pt32 += __shfl_down_sync(0xffffffffu, pt32, off);
        ce32 += __shfl_down_sync(0xffffffffu, ce32, off);
    }
    __shared__ double s_pt[8];
    __shared__ double s_ce[8];
    if (lane == 0) { s_pt[wid] = (double)pt32; s_ce[wid] = (double)ce32; }
    __syncthreads();
    __shared__ bool is_last;
    if (tid == 0) {
        double bpt = 0.0, bce = 0.0;
        #pragma unroll
        for (int i = 0; i < 8; i++) { bpt += s_pt[i]; bce += s_ce[i]; }
        g_pt[blockIdx.x] = bpt;
        g_ce[blockIdx.x] = bce;
        __threadfence();
        const unsigned int arrived = atomicAdd(&g_count, 1u);
        is_last = (arrived == NBLK - 1);
    }
    __syncthreads();

    // Last block: final fixed-order reduction -> scalar loss.
    if (is_last) {
        double fpt = 0.0, fce = 0.0;
        for (int i = tid; i < NBLK; i += 256) { fpt += g_pt[i]; fce += g_ce[i]; }
        __shared__ double r_pt[256];
        __shared__ double r_ce[256];
        r_pt[tid] = fpt;
        r_ce[tid] = fce;
        __syncthreads();
        #pragma unroll
        for (int off = 128; off > 0; off >>= 1) {
            if (tid < off) {
                r_pt[tid] += r_pt[tid + off];
                r_ce[tid] += r_ce[tid + off];
            }
            __syncthreads();
        }
        if (tid == 0) {
            const double pt_loss = r_pt[0] / ((double)B * (double)NCOLS);
            const double ce_loss = -r_ce[0] / (double)B;
            out[0] = (float)(ce_loss + pt_loss);
            g_count = 0;   // reset for next graph replay
        }
    }
}

extern "C" void kernel_launch(void* const* d_in, const int* in_sizes, int n_in,
                              void* d_out, int out_size) {
    const float* y_true = (const float*)d_in[0];
    const float* target = (const float*)d_in[1];
    const int B = in_sizes[0] / NCOLS;

    fused_kernel<<<NBLK, 256>>>(y_true, target, (float*)d_out, B);
}

// round 17
// speedup vs baseline: 1.0428x; 1.0027x over previous
#include <cuda_runtime.h>
#include <cstdint>
#include <math.h>

// y_true [B,1024] fp32, target [B,1024] fp32 -> scalar fp32 loss.
#define NCOLS   1024
#define NBLK    444            // 148 SMs * 3 resident blocks (80 regs/thread)
#define NWARPS  (NBLK * 8)

__device__ double g_pt[NBLK];
__device__ double g_ce[NBLK];
__device__ unsigned int g_count = 0;   // last-block-done counter

__device__ __forceinline__ float wval(int x) {
    const int pc = __popc(x);
    float w = ((pc & 1) ? 6.0f       : 1.0f)
            * ((pc & 2) ? 36.0f      : 1.0f)
            * ((pc & 4) ? 1296.0f    : 1.0f)
            * ((pc & 8) ? 1679616.0f : 1.0f);
    return (x == 0) ? 0.0f : w;   // 6^popc(x), zeroed at x==0; exact in fp32
}

// ---------------------------------------------------------------------------
// FINAL (best measured, R11/R14): one-row software pipeline. Everything
// consumed in iteration i was issued in iteration i-1, so REDUX and FMA
// phases never wait on memory. Per iteration:
//   (1) issue target loads row b+1   (2) REDUX on carried (best,bidx) -> t_b
//   (3) FMA carried yv (row b)       (4) issue y loads row b+1
//   (5) per-lane compare on (1)'s data -> carried (best,bidx) for b+1
// Proven invariants (16 rounds of evidence):
//   - loads must stay front-batched (8 LDG.128/batch); interleaving loses
//   - strided row map (b += NWARPS) preserves L2/DRAM band locality
//   - 3 blocks/SM with register buffers beats higher occupancy w/o them
// ---------------------------------------------------------------------------
__global__ void __launch_bounds__(256, 3)
fused_kernel(const float* __restrict__ y, const float* __restrict__ target,
             float* __restrict__ out, int B) {
    // W[p][i] = wval(i ^ p): weights of columns 4g..4g+3 for class t are the
    // aligned float4 at W[t&3][4*(g ^ (t>>2))] -> one conflict-free LDS.128.
    __shared__ float W[4][NCOLS];
    const int tid  = threadIdx.x;
    const int lane = tid & 31;
    const int wid  = tid >> 5;
    for (int i = tid; i < NCOLS; i += 256) {
        #pragma unroll
        for (int p = 0; p < 4; p++) W[p][i] = wval(i ^ p);
    }
    __syncthreads();

    const int gwarp = blockIdx.x * 8 + wid;
    float pt32 = 0.0f;   // fp32 within-warp is exact enough (budget ~140 abs)
    float ce32 = 0.0f;

    int   b = gwarp;
    float best = -1.0f;
    int   bidx = 0;
    float4 yv[8];

    if (b < B) {
        // Prologue: load row b's target + y; per-lane argmax of target.
        const float4* tp = reinterpret_cast<const float4*>(target + (size_t)b * NCOLS);
        const float4* yp = reinterpret_cast<const float4*>(y      + (size_t)b * NCOLS);
        float4 tv[8];
        #pragma unroll
        for (int i = 0; i < 8; i++) {
            tv[i] = __ldcs(&tp[i * 32 + lane]);
            yv[i] = __ldcs(&yp[i * 32 + lane]);
        }
        #pragma unroll
        for (int i = 0; i < 8; i++) {
            const int base = (i * 32 + lane) * 4;
            if (tv[i].x > best) { best = tv[i].x; bidx = base;     }
            if (tv[i].y > best) { best = tv[i].y; bidx = base + 1; }
            if (tv[i].z > best) { best = tv[i].z; bidx = base + 2; }
            if (tv[i].w > best) { best = tv[i].w; bidx = base + 3; }
        }

        // Steady-state pipeline.
        for (;;) {
            int bn = b + NWARPS;
            const bool last = (bn >= B);
            if (last) bn = b;   // clamped prefetch: loaded but never accumulated
            const float4* tpn = reinterpret_cast<const float4*>(target + (size_t)bn * NCOLS);
            const float4* ypn = reinterpret_cast<const float4*>(y      + (size_t)bn * NCOLS);

            // (1) issue next target row loads (front-batched).
            float4 tn[8];
            #pragma unroll
            for (int i = 0; i < 8; i++) tn[i] = __ldcs(&tpn[i * 32 + lane]);

            // (2) cross-lane argmax for row b from carried (best,bidx): no wait.
            // Exact: positive floats are uint-monotonic; first-occurrence ties
            // via min index among max holders.
            const unsigned int mybits  = __float_as_uint(best);
            const unsigned int maxbits = __reduce_max_sync(0xffffffffu, mybits);
            const unsigned int cand    = (mybits == maxbits) ? (unsigned int)bidx
                                                             : 0xffffffffu;
            const int t  = (int)__reduce_min_sync(0xffffffffu, cand);
            const int tg = t >> 2;
            const float* Wt = W[t & 3];

            // (3) FMA carried yv (row b, loaded one iteration ago): no wait.
            float s0 = 0.f, s1 = 0.f, s2 = 0.f, s3 = 0.f;
            float yt = -1.0f;
            #pragma unroll
            for (int i = 0; i < 8; i++) {
                const int c4 = i * 32 + lane;
                const float4 w4 = *reinterpret_cast<const float4*>(&Wt[(c4 ^ tg) << 2]);
                s0 += w4.x * yv[i].x;
                s1 += w4.y * yv[i].y;
                s2 += w4.z * yv[i].z;
                s3 += w4.w * yv[i].w;
                if (c4 == tg) {
                    yt = (t & 1) ? ((t & 2) ? yv[i].w : yv[i].y)
                                 : ((t & 2) ? yv[i].z : yv[i].x);
                }
            }
            pt32 += (s0 + s1) + (s2 + s3);
            if (yt >= 0.0f) ce32 += __logf(yt + 1e-8f);   // one lane per warp

            // (4) issue next y row loads (front-batched; full iter to land).
            #pragma unroll
            for (int i = 0; i < 8; i++) yv[i] = __ldcs(&ypn[i * 32 + lane]);

            // (5) per-lane compare on next target row (wait covered by 2-4).
            best = -1.0f; bidx = 0;
            #pragma unroll
            for (int i = 0; i < 8; i++) {
                const int base = (i * 32 + lane) * 4;
                if (tn[i].x > best) { best = tn[i].x; bidx = base;     }
                if (tn[i].y > best) { best = tn[i].y; bidx = base + 1; }
                if (tn[i].z > best) { best = tn[i].z; bidx = base + 2; }
                if (tn[i].w > best) { best = tn[i].w; bidx = base + 3; }
            }

            if (last) break;
            b = bn;
        }
    }

    // Warp reduce in fp32 (fixed order), promote to double for partials.
    #pragma unroll
    for (int off = 16; off > 0; off >>= 1) {
        pt32 += __shfl_down_sync(0xffffffffu, pt32, off);
        ce32 += __shfl_down_sync(0xffffffffu, ce32, off);
    }
    __shared__ double s_pt[8];
    __shared__ double s_ce[8];
    if (lane == 0) { s_pt[wid] = (double)pt32; s_ce[wid] = (double)ce32; }
    __syncthreads();
    __shared__ bool is_last;
    if (tid == 0) {
        double bpt = 0.0, bce = 0.0;
        #pragma unroll
        for (int i = 0; i < 8; i++) { bpt += s_pt[i]; bce += s_ce[i]; }
        g_pt[blockIdx.x] = bpt;
        g_ce[blockIdx.x] = bce;
        __threadfence();
        const unsigned int arrived = atomicAdd(&g_count, 1u);
        is_last = (arrived == NBLK - 1);
    }
    __syncthreads();

    // Last block: final fixed-order (deterministic) reduction -> scalar loss.
    if (is_last) {
        double fpt = 0.0, fce = 0.0;
        for (int i = tid; i < NBLK; i += 256) { fpt += g_pt[i]; fce += g_ce[i]; }
        __shared__ double r_pt[256];
        __shared__ double r_ce[256];
        r_pt[tid] = fpt;
        r_ce[tid] = fce;
        __syncthreads();
        #pragma unroll
        for (int off = 128; off > 0; off >>= 1) {
            if (tid < off) {
                r_pt[tid] += r_pt[tid + off];
                r_ce[tid] += r_ce[tid + off];
            }
            __syncthreads();
        }
        if (tid == 0) {
            const double pt_loss = r_pt[0] / ((double)B * (double)NCOLS);
            const double ce_loss = -r_ce[0] / (double)B;
            out[0] = (float)(ce_loss + pt_loss);
            g_count = 0;   // reset for next graph replay
        }
    }
}

extern "C" void kernel_launch(void* const* d_in, const int* in_sizes, int n_in,
                              void* d_out, int out_size) {
    const float* y_true = (const float*)d_in[0];
    const float* target = (const float*)d_in[1];
    const int B = in_sizes[0] / NCOLS;

    fused_kernel<<<NBLK, 256>>>(y_true, target, (float*)d_out, B);
}